// round 5
// baseline (speedup 1.0000x reference)
#include <cuda_runtime.h>

#define T_ 1024
#define B_ 128
typedef unsigned long long ull;

// ---------------- packed f32x2 helpers (Blackwell FFMA2) ----------------
__device__ __forceinline__ ull pack2(float v) {
    ull r; unsigned u = __float_as_uint(v);
    asm("mov.b64 %0, {%1, %1};" : "=l"(r) : "r"(u));
    return r;
}
__device__ __forceinline__ void fma2(ull &acc, ull a, ull b) {
    asm("fma.rn.f32x2 %0, %1, %2, %0;" : "+l"(acc) : "l"(a), "l"(b));
}
__device__ __forceinline__ float2 unpack2(ull v) {
    unsigned lo, hi;
    asm("mov.b64 {%0, %1}, %2;" : "=r"(lo), "=r"(hi) : "l"(v));
    return make_float2(__uint_as_float(lo), __uint_as_float(hi));
}

// ---------------- scratch (device globals; no allocations) ----------------
__device__ int   g_chars[B_*T_];
__device__ float g_w1t[3*400*128];               // [k][ci][co]
__device__ float g_w2t[3*128*64];
__device__ float g_w3t[3*64*32];
__device__ float g_gpart[B_*3*128];
__device__ float g_sty[B_*80*3*128];             // [b][char][k][co]
__device__ float g_x1[B_*T_*128];
__device__ float g_x2[B_*T_*64];
__device__ float g_x3[B_*T_*32];
__device__ float g_ab1[B_*128], g_dd1[B_*128];
__device__ float g_ab2[B_*64],  g_dd2[B_*64];
__device__ float g_ab3[B_*32],  g_dd3[B_*32];

// ---------------- weight transpose: w[O][I][3] -> wt[k][I][O] ----------------
__global__ void wtrans_k(const float* __restrict__ w, int O, int I, int which) {
    float* wt = (which == 0) ? g_w1t : (which == 1) ? g_w2t : g_w3t;
    int idx = blockIdx.x * blockDim.x + threadIdx.x;
    int total = O * I * 3;
    if (idx < total) {
        int k = idx % 3;
        int i = (idx / 3) % I;
        int o = idx / (3 * I);
        wt[(k * I + i) * O + o] = w[idx];
    }
}

// ---------------- argmax, warp per (t,b), lowest-index tie-break ----------------
__global__ void argmax_k(const float* __restrict__ inp) {
    int gw = (blockIdx.x * blockDim.x + threadIdx.x) >> 5;
    int lane = threadIdx.x & 31;
    if (gw >= T_ * B_) return;
    int t = gw >> 7;
    int b = gw & 127;
    const float4* row = (const float4*)(inp + (t * B_ + b) * 80);
    float best = -3.4e38f; int bi = 0x7FFFFFFF;
    if (lane < 20) {
        float4 v = row[lane];
        best = v.x; bi = 4 * lane;
        if (v.y > best) { best = v.y; bi = 4 * lane + 1; }
        if (v.z > best) { best = v.z; bi = 4 * lane + 2; }
        if (v.w > best) { best = v.w; bi = 4 * lane + 3; }
    }
    for (int off = 16; off; off >>= 1) {
        float ov = __shfl_down_sync(0xFFFFFFFFu, best, off);
        int   oi = __shfl_down_sync(0xFFFFFFFFu, bi, off);
        if (ov > best || (ov == best && oi < bi)) { best = ov; bi = oi; }
    }
    if (lane == 0) g_chars[b * T_ + t] = bi;
}

// ---------------- stylepre[b][c][k][co] ----------------
__global__ void stylepre_k(const float* __restrict__ char_style) {
    __shared__ float sw[64 * 128];
    int k = blockIdx.x, b = blockIdx.y, co = threadIdx.x;
    int base = (k * 400 + 336) * 128;
    for (int i = threadIdx.x; i < 64 * 128; i += 128) sw[i] = g_w1t[base + i];
    __syncthreads();
    for (int c = 0; c < 80; c++) {
        const float* cs = char_style + (b * 80 + c) * 64;
        float a = 0.f;
        #pragma unroll 8
        for (int ci = 0; ci < 64; ci++) a = fmaf(cs[ci], sw[ci * 128 + co], a);
        g_sty[((b * 80 + c) * 3 + k) * 128 + co] = a;
    }
}

// ---------------- gpart[b][k][co] ----------------
__global__ void gpart_k(const float* __restrict__ g_style) {
    __shared__ float sg[256];
    int b = blockIdx.x, co = threadIdx.x;
    for (int i = co; i < 256; i += 128) sg[i] = g_style[b * 256 + i];
    __syncthreads();
    float a0 = 0.f, a1 = 0.f, a2 = 0.f;
    for (int ci = 0; ci < 256; ci++) {
        float v = sg[ci];
        a0 = fmaf(v, g_w1t[(0 * 400 + 80 + ci) * 128 + co], a0);
        a1 = fmaf(v, g_w1t[(1 * 400 + 80 + ci) * 128 + co], a1);
        a2 = fmaf(v, g_w1t[(2 * 400 + 80 + ci) * 128 + co], a2);
    }
    g_gpart[(b * 3 + 0) * 128 + co] = a0;
    g_gpart[(b * 3 + 1) * 128 + co] = a1;
    g_gpart[(b * 3 + 2) * 128 + co] = a2;
}

// ---------------- conv1: 80-ch GEMM; dup-pair smem; 4co x 8t per thread ----------------
__global__ __launch_bounds__(256) void conv1_k(const float* __restrict__ inp,
                                               const float* __restrict__ bias) {
    int b = blockIdx.y;
    int t0 = blockIdx.x * 64;
    int lane = threadIdx.x;     // 0..31: co quad q = 4*lane covers 128 co
    int ty = threadIdx.y;       // 0..7 : 8 t each
    __shared__ ull sxd[66][80];
    __shared__ int sch[66];
    int tid = ty * 32 + lane;
    for (int i = tid; i < 66 * 80; i += 256) {
        int r = i / 80, ci = i - r * 80;
        int t = t0 - 1 + r;
        float v = (t >= 0 && t < T_) ? inp[(t * B_ + b) * 80 + ci] : 0.f;
        sxd[r][ci] = pack2(v);
    }
    for (int i = tid; i < 66; i += 256) {
        int t = t0 - 1 + i;
        sch[i] = (t >= 0 && t < T_) ? g_chars[b * T_ + t] : 0;
    }
    __syncthreads();

    int rbase = ty * 8;
    int q = 4 * lane;
    ull acc0[8], acc1[8];
    #pragma unroll
    for (int i = 0; i < 8; i++) { acc0[i] = 0ull; acc1[i] = 0ull; }

    for (int ci = 0; ci < 80; ci++) {
        ull px[10];
        #pragma unroll
        for (int r = 0; r < 10; r++) px[r] = sxd[rbase + r][ci];
        #pragma unroll
        for (int k = 0; k < 3; k++) {
            ulonglong2 w = *(const ulonglong2*)(g_w1t + (k * 400 + ci) * 128 + q);
            #pragma unroll
            for (int tt = 0; tt < 8; tt++) {
                fma2(acc0[tt], px[tt + k], w.x);
                fma2(acc1[tt], px[tt + k], w.y);
            }
        }
    }

    float4 bz = *(const float4*)(bias + q);
    #pragma unroll
    for (int tt = 0; tt < 8; tt++) {
        int t = t0 + rbase + tt;
        float2 lo = unpack2(acc0[tt]);
        float2 hi = unpack2(acc1[tt]);
        float4 a = make_float4(lo.x + bz.x, lo.y + bz.y, hi.x + bz.z, hi.y + bz.w);
        #pragma unroll
        for (int k = 0; k < 3; k++) {
            int tp = t + k - 1;
            if (tp >= 0 && tp < T_) {
                float4 g = *(const float4*)(g_gpart + (b * 3 + k) * 128 + q);
                float4 s = *(const float4*)(g_sty + ((b * 80 + sch[rbase + tt + k]) * 3 + k) * 128 + q);
                a.x += g.x + s.x; a.y += g.y + s.y;
                a.z += g.z + s.z; a.w += g.w + s.w;
            }
        }
        *(float4*)(g_x1 + (b * T_ + t) * 128 + q) = a;
    }
}

// ---------------- GN stats -> fused affine, coalesced ----------------
template<int C, int G, int WHICH>
__global__ void stats_k(const float* __restrict__ gs, const float* __restrict__ gb) {
    const float* x = (WHICH == 1) ? g_x1 : (WHICH == 2) ? g_x2 : g_x3;
    float* ab = (WHICH == 1) ? g_ab1 : (WHICH == 2) ? g_ab2 : g_ab3;
    float* dd = (WHICH == 1) ? g_dd1 : (WHICH == 2) ? g_dd2 : g_dd3;
    int b = blockIdx.x;
    int tid = threadIdx.x;              // 512 threads
    int c = tid % C;
    int tg = tid / C;
    const int TGS = 512 / C;
    const float* p = x + b * T_ * C + c;
    float s = 0.f, q = 0.f;
    for (int t = tg; t < T_; t += TGS) {
        float v = p[t * C];
        s += v; q = fmaf(v, v, q);
    }
    __shared__ float ss[512], sq[512];
    __shared__ float sS[C], sQ[C];
    ss[tid] = s; sq[tid] = q;
    __syncthreads();
    if (tid < C) {
        float S = 0.f, Q = 0.f;
        #pragma unroll
        for (int j = 0; j < TGS; j++) { S += ss[j * C + c]; Q += sq[j * C + c]; }
        sS[c] = S; sQ[c] = Q;
    }
    __syncthreads();
    if (tid < C) {
        int g0 = (c / G) * G;
        float S = 0.f, Q = 0.f;
        #pragma unroll
        for (int j = 0; j < G; j++) { S += sS[g0 + j]; Q += sQ[g0 + j]; }
        float n = (float)(G * T_);
        float mu = S / n;
        float var = Q / n - mu * mu;
        float a = rsqrtf(var + 1e-5f) * gs[c];
        ab[b * C + c] = a;
        dd[b * C + c] = gb[c] - mu * a;
    }
}

// ---------------- conv2: 128->64; dup-pair smem; 4co x 4t per thread ----------------
__global__ __launch_bounds__(128) void conv2_k(const float* __restrict__ bias) {
    int b = blockIdx.y;
    int t0 = blockIdx.x * 32;
    int lane = threadIdx.x;
    int quad = lane & 15;        // co = 4*quad (64 co)
    int sub = lane >> 4;         // 0..1
    int ty = threadIdx.y;        // 0..3
    __shared__ ull sxd[34][128];
    int tid = ty * 32 + lane;
    const float* ab = g_ab1 + b * 128;
    const float* dd = g_dd1 + b * 128;
    for (int i = tid; i < 34 * 128; i += 128) {
        int r = i >> 7, ci = i & 127;
        int t = t0 - 1 + r;
        float v = 0.f;
        if (t >= 0 && t < T_)
            v = fmaxf(fmaf(ab[ci], g_x1[(b * T_ + t) * 128 + ci], dd[ci]), 0.f);
        sxd[r][ci] = pack2(v);
    }
    __syncthreads();

    int rbase = (ty * 2 + sub) * 4;
    int q = 4 * quad;
    ull acc0[4], acc1[4];
    #pragma unroll
    for (int i = 0; i < 4; i++) { acc0[i] = 0ull; acc1[i] = 0ull; }

    for (int ci = 0; ci < 128; ci++) {
        ull px[6];
        #pragma unroll
        for (int r = 0; r < 6; r++) px[r] = sxd[rbase + r][ci];
        #pragma unroll
        for (int k = 0; k < 3; k++) {
            ulonglong2 w = *(const ulonglong2*)(g_w2t + (k * 128 + ci) * 64 + q);
            #pragma unroll
            for (int tt = 0; tt < 4; tt++) {
                fma2(acc0[tt], px[tt + k], w.x);
                fma2(acc1[tt], px[tt + k], w.y);
            }
        }
    }

    float4 bz = *(const float4*)(bias + q);
    #pragma unroll
    for (int tt = 0; tt < 4; tt++) {
        int t = t0 + rbase + tt;
        float2 lo = unpack2(acc0[tt]);
        float2 hi = unpack2(acc1[tt]);
        float4 a = make_float4(lo.x + bz.x, lo.y + bz.y, hi.x + bz.z, hi.y + bz.w);
        *(float4*)(g_x2 + (b * T_ + t) * 64 + q) = a;
    }
}

// ---------------- conv3: 64->32; dup-pair smem; 4co x 2t per thread ----------------
__global__ __launch_bounds__(256) void conv3_k(const float* __restrict__ bias) {
    int b = blockIdx.y;
    int t0 = blockIdx.x * 64;
    int lane = threadIdx.x;
    int quad = lane & 7;         // co = 4*quad (32 co)
    int sub = lane >> 3;         // 0..3
    int ty = threadIdx.y;        // 0..7
    __shared__ ull sxd[66][64];
    int tid = ty * 32 + lane;
    const float* ab = g_ab2 + b * 64;
    const float* dd = g_dd2 + b * 64;
    for (int i = tid; i < 66 * 64; i += 256) {
        int r = i >> 6, ci = i & 63;
        int t = t0 - 1 + r;
        float v = 0.f;
        if (t >= 0 && t < T_)
            v = fmaxf(fmaf(ab[ci], g_x2[(b * T_ + t) * 64 + ci], dd[ci]), 0.f);
        sxd[r][ci] = pack2(v);
    }
    __syncthreads();

    int rbase = (ty * 4 + sub) * 2;
    int q = 4 * quad;
    ull acc0[2], acc1[2];
    acc0[0] = acc0[1] = acc1[0] = acc1[1] = 0ull;

    for (int ci = 0; ci < 64; ci++) {
        ull px[4];
        #pragma unroll
        for (int r = 0; r < 4; r++) px[r] = sxd[rbase + r][ci];
        #pragma unroll
        for (int k = 0; k < 3; k++) {
            ulonglong2 w = *(const ulonglong2*)(g_w3t + (k * 64 + ci) * 32 + q);
            #pragma unroll
            for (int tt = 0; tt < 2; tt++) {
                fma2(acc0[tt], px[tt + k], w.x);
                fma2(acc1[tt], px[tt + k], w.y);
            }
        }
    }

    float4 bz = *(const float4*)(bias + q);
    #pragma unroll
    for (int tt = 0; tt < 2; tt++) {
        int t = t0 + rbase + tt;
        float2 lo = unpack2(acc0[tt]);
        float2 hi = unpack2(acc1[tt]);
        float4 a = make_float4(lo.x + bz.x, lo.y + bz.y, hi.x + bz.z, hi.y + bz.w);
        *(float4*)(g_x3 + (b * T_ + t) * 32 + q) = a;
    }
}

// ---------------- final: GN3+relu + 1x1 conv + affine, warp per t ----------------
__global__ void final_k(const float* __restrict__ w4, const float* __restrict__ b4,
                        const float* __restrict__ mean, const float* __restrict__ stdv,
                        float* __restrict__ out) {
    int b = blockIdx.y;
    int w = threadIdx.x >> 5, lane = threadIdx.x & 31;
    float wv = w4[lane];
    float a = g_ab3[b * 32 + lane], d0 = g_dd3[b * 32 + lane];
    float bb = b4[0], me = mean[0], sc = stdv[0];
    int tbase = blockIdx.x * 128 + w * 16;
    for (int i = 0; i < 16; i++) {
        int t = tbase + i;
        float v = fmaxf(fmaf(a, g_x3[(b * T_ + t) * 32 + lane], d0), 0.f) * wv;
        #pragma unroll
        for (int off = 16; off; off >>= 1) v += __shfl_xor_sync(0xFFFFFFFFu, v, off);
        if (lane == 0) out[t * B_ + b] = fmaf(v + bb, sc, me);
    }
}

// ---------------- launcher ----------------
extern "C" void kernel_launch(void* const* d_in, const int* in_sizes, int n_in,
                              void* d_out, int out_size) {
    (void)in_sizes; (void)n_in; (void)out_size;
    const float* input      = (const float*)d_in[0];
    const float* g_style    = (const float*)d_in[1];
    const float* char_style = (const float*)d_in[3];
    const float* w1 = (const float*)d_in[4];
    const float* b1 = (const float*)d_in[5];
    const float* gs1 = (const float*)d_in[6];
    const float* gb1 = (const float*)d_in[7];
    const float* w2 = (const float*)d_in[8];
    const float* b2 = (const float*)d_in[9];
    const float* gs2 = (const float*)d_in[10];
    const float* gb2 = (const float*)d_in[11];
    const float* w3 = (const float*)d_in[12];
    const float* b3 = (const float*)d_in[13];
    const float* gs3 = (const float*)d_in[14];
    const float* gb3 = (const float*)d_in[15];
    const float* w4 = (const float*)d_in[16];
    const float* b4 = (const float*)d_in[17];
    const float* mean = (const float*)d_in[18];
    const float* stdv = (const float*)d_in[19];
    float* out = (float*)d_out;

    wtrans_k<<<(128 * 400 * 3 + 255) / 256, 256>>>(w1, 128, 400, 0);
    wtrans_k<<<(64 * 128 * 3 + 255) / 256, 256>>>(w2, 64, 128, 1);
    wtrans_k<<<(32 * 64 * 3 + 255) / 256, 256>>>(w3, 32, 64, 2);
    argmax_k<<<(T_ * B_ * 32) / 256, 256>>>(input);
    stylepre_k<<<dim3(3, B_), 128>>>(char_style);
    gpart_k<<<B_, 128>>>(g_style);
    conv1_k<<<dim3(T_ / 64, B_), dim3(32, 8)>>>(input, b1);
    stats_k<128, 4, 1><<<B_, 512>>>(gs1, gb1);
    conv2_k<<<dim3(T_ / 32, B_), dim3(32, 4)>>>(b2);
    stats_k<64, 2, 2><<<B_, 512>>>(gs2, gb2);
    conv3_k<<<dim3(T_ / 64, B_), dim3(32, 8)>>>(b3);
    stats_k<32, 1, 3><<<B_, 512>>>(gs3, gb3);
    final_k<<<dim3(T_ / 128, B_), 256>>>(w4, b4, mean, stdv, out);
}

// round 6
// speedup vs baseline: 1.2637x; 1.2637x over previous
#include <cuda_runtime.h>

#define T_ 1024
#define B_ 128

// ---------------- tf32 helpers ----------------
__device__ __forceinline__ unsigned tf32r(float f) {
    unsigned r; asm("cvt.rna.tf32.f32 %0, %1;" : "=r"(r) : "f"(f)); return r;
}
__device__ __forceinline__ float tf32f(float f) {
    return __uint_as_float(tf32r(f));
}
// m16n8k8 tf32 mma, fp32 accumulate. A row-major frag, B col-major frag.
__device__ __forceinline__ void mma_tf32(float c[4], unsigned a0, unsigned a1,
                                         unsigned a2, unsigned a3,
                                         unsigned b0, unsigned b1) {
    asm("mma.sync.aligned.m16n8k8.row.col.f32.tf32.tf32.f32 "
        "{%0,%1,%2,%3}, {%4,%5,%6,%7}, {%8,%9}, {%0,%1,%2,%3};"
        : "+f"(c[0]), "+f"(c[1]), "+f"(c[2]), "+f"(c[3])
        : "r"(a0), "r"(a1), "r"(a2), "r"(a3), "r"(b0), "r"(b1));
}

// ---------------- scratch (device globals; no allocations) ----------------
__device__ int   g_chars[B_*T_];
__device__ float g_w1t[3*80*128];                // conv1 real-input weights [k][ci<80][co] (tf32)
__device__ float g_w1s[3*320*128];               // conv1 style weights [k][ci-80][co] (tf32)
__device__ float g_w2t[3*128*64];                // (tf32)
__device__ float g_w3t[3*64*32];                 // (tf32)
__device__ float g_gpart[B_*3*128];
__device__ float g_sty[B_*80*3*128];             // sty+gpart, [b][char][k][co]
__device__ float g_add[B_*T_*128];               // bias + style/gpart terms per (b,t,co)
__device__ float g_x1[B_*T_*128];
__device__ float g_x2[B_*T_*64];
__device__ float g_x3[B_*T_*32];
__device__ float g_ab1[B_*128], g_dd1[B_*128];
__device__ float g_ab2[B_*64],  g_dd2[B_*64];
__device__ float g_ab3[B_*32],  g_dd3[B_*32];

// ---------------- weight transpose + tf32 round ----------------
// w1 [128][400][3] -> g_w1t [k][ci<80][128], g_w1s [k][ci-80][128]
__global__ void wtrans1_k(const float* __restrict__ w) {
    int idx = blockIdx.x * blockDim.x + threadIdx.x;
    if (idx >= 128 * 400 * 3) return;
    int k = idx % 3;
    int i = (idx / 3) % 400;
    int o = idx / (3 * 400);
    float v = tf32f(w[idx]);
    if (i < 80) g_w1t[(k * 80 + i) * 128 + o] = v;
    else        g_w1s[(k * 320 + (i - 80)) * 128 + o] = v;
}
__global__ void wtrans_k(const float* __restrict__ w, int O, int I, int which) {
    float* wt = (which == 1) ? g_w2t : g_w3t;
    int idx = blockIdx.x * blockDim.x + threadIdx.x;
    if (idx >= O * I * 3) return;
    int k = idx % 3;
    int i = (idx / 3) % I;
    int o = idx / (3 * I);
    wt[(k * I + i) * O + o] = tf32f(w[idx]);
}

// ---------------- argmax, warp per (t,b), lowest-index tie-break ----------------
__global__ void argmax_k(const float* __restrict__ inp) {
    int gw = (blockIdx.x * blockDim.x + threadIdx.x) >> 5;
    int lane = threadIdx.x & 31;
    if (gw >= T_ * B_) return;
    int t = gw >> 7;
    int b = gw & 127;
    const float4* row = (const float4*)(inp + (t * B_ + b) * 80);
    float best = -3.4e38f; int bi = 0x7FFFFFFF;
    if (lane < 20) {
        float4 v = row[lane];
        best = v.x; bi = 4 * lane;
        if (v.y > best) { best = v.y; bi = 4 * lane + 1; }
        if (v.z > best) { best = v.z; bi = 4 * lane + 2; }
        if (v.w > best) { best = v.w; bi = 4 * lane + 3; }
    }
    for (int off = 16; off; off >>= 1) {
        float ov = __shfl_down_sync(0xFFFFFFFFu, best, off);
        int   oi = __shfl_down_sync(0xFFFFFFFFu, bi, off);
        if (ov > best || (ov == best && oi < bi)) { best = ov; bi = oi; }
    }
    if (lane == 0) g_chars[b * T_ + t] = bi;
}

// ---------------- gpart[b][k][co] from g_style (style rows 0..255 of w1s) ----------------
__global__ void gpart_k(const float* __restrict__ g_style) {
    __shared__ float sg[256];
    int b = blockIdx.x, co = threadIdx.x;
    for (int i = co; i < 256; i += 128) sg[i] = g_style[b * 256 + i];
    __syncthreads();
    float a0 = 0.f, a1 = 0.f, a2 = 0.f;
    for (int ci = 0; ci < 256; ci++) {
        float v = sg[ci];
        a0 = fmaf(v, g_w1s[(0 * 320 + ci) * 128 + co], a0);
        a1 = fmaf(v, g_w1s[(1 * 320 + ci) * 128 + co], a1);
        a2 = fmaf(v, g_w1s[(2 * 320 + ci) * 128 + co], a2);
    }
    g_gpart[(b * 3 + 0) * 128 + co] = a0;
    g_gpart[(b * 3 + 1) * 128 + co] = a1;
    g_gpart[(b * 3 + 2) * 128 + co] = a2;
}

// ---------------- stylepre: g_sty = char_style GEMM + gpart (style rows 256..319) ----------------
__global__ void stylepre_k(const float* __restrict__ char_style) {
    __shared__ float sw[64 * 128];
    int k = blockIdx.x, b = blockIdx.y, co = threadIdx.x;
    int base = (k * 320 + 256) * 128;
    for (int i = threadIdx.x; i < 64 * 128; i += 128) sw[i] = g_w1s[base + i];
    __syncthreads();
    float gp = g_gpart[(b * 3 + k) * 128 + co];
    for (int c = 0; c < 80; c++) {
        const float* cs = char_style + (b * 80 + c) * 64;
        float a = gp;
        #pragma unroll 8
        for (int ci = 0; ci < 64; ci++) a = fmaf(cs[ci], sw[ci * 128 + co], a);
        g_sty[((b * 80 + c) * 3 + k) * 128 + co] = a;
    }
}

// ---------------- g_add[b][t][co] = bias + sum_k valid * (sty+gpart) ----------------
__global__ void add_k(const float* __restrict__ bias) {
    int t = blockIdx.x, b = blockIdx.y, co = threadIdx.x;
    float a = bias[co];
    #pragma unroll
    for (int k = 0; k < 3; k++) {
        int tp = t + k - 1;
        if (tp >= 0 && tp < T_) {
            int ch = g_chars[b * T_ + tp];
            a += g_sty[((b * 80 + ch) * 3 + k) * 128 + co];
        }
    }
    g_add[(b * T_ + t) * 128 + co] = a;
}

// ================ conv1: tf32 MMA, M=64 t, N=128 co, K=240 ================
// 8 warps: wm=wid&3 (m16 each), nh=wid>>2 (64 co each). B chunks of 40 K-rows.
__global__ __launch_bounds__(256) void conv1_k(const float* __restrict__ inp) {
    __shared__ float sA[66 * 84];       // [t 0..65][ci 0..79], stride 84
    __shared__ float sB[40 * 136];      // [krow][co], stride 136
    int b = blockIdx.y, t0 = blockIdx.x * 64;
    int tid = threadIdx.x, lane = tid & 31, wid = tid >> 5;
    int wm = wid & 3, nh = wid >> 2;

    for (int i = tid; i < 66 * 80; i += 256) {
        int r = i / 80, ci = i - r * 80;
        int t = t0 - 1 + r;
        float v = (t >= 0 && t < T_) ? inp[(t * B_ + b) * 80 + ci] : 0.f;
        sA[r * 84 + ci] = tf32f(v);
    }

    float acc[8][4];
    #pragma unroll
    for (int nt = 0; nt < 8; nt++)
        #pragma unroll
        for (int j = 0; j < 4; j++) acc[nt][j] = 0.f;

    for (int c = 0; c < 6; c++) {           // chunk: tap=c>>1, ci base=(c&1)*40
        int tap = c >> 1, cib = (c & 1) * 40;
        __syncthreads();
        for (int i = tid; i < 40 * 128; i += 256) {
            int kr = i >> 7, co = i & 127;
            sB[kr * 136 + co] = g_w1t[((tap * 80 + cib) + kr) * 128 + co];
        }
        __syncthreads();
        int arow = 16 * wm + (lane >> 2) + tap;
        int bcol = nh * 64 + (lane >> 2);
        #pragma unroll
        for (int ks = 0; ks < 5; ks++) {
            int cb = cib + ks * 8 + (lane & 3);
            unsigned a0 = __float_as_uint(sA[arow * 84 + cb]);
            unsigned a1 = __float_as_uint(sA[(arow + 8) * 84 + cb]);
            unsigned a2 = __float_as_uint(sA[arow * 84 + cb + 4]);
            unsigned a3 = __float_as_uint(sA[(arow + 8) * 84 + cb + 4]);
            int brow = ks * 8 + (lane & 3);
            #pragma unroll
            for (int nt = 0; nt < 8; nt++) {
                unsigned b0 = __float_as_uint(sB[brow * 136 + bcol + nt * 8]);
                unsigned b1 = __float_as_uint(sB[(brow + 4) * 136 + bcol + nt * 8]);
                mma_tf32(acc[nt], a0, a1, a2, a3, b0, b1);
            }
        }
    }

    int trow = t0 + 16 * wm + (lane >> 2);
    int colb = nh * 64 + 2 * (lane & 3);
    #pragma unroll
    for (int nt = 0; nt < 8; nt++) {
        int col = colb + nt * 8;
        int idx = (b * T_ + trow) * 128 + col;
        float2 ad = *(const float2*)(g_add + idx);
        float2 o = make_float2(acc[nt][0] + ad.x, acc[nt][1] + ad.y);
        *(float2*)(g_x1 + idx) = o;
        int idx8 = idx + 8 * 128;
        float2 ad8 = *(const float2*)(g_add + idx8);
        float2 o8 = make_float2(acc[nt][2] + ad8.x, acc[nt][3] + ad8.y);
        *(float2*)(g_x1 + idx8) = o8;
    }
}

// ---------------- GN stats -> fused affine, coalesced ----------------
template<int C, int G, int WHICH>
__global__ void stats_k(const float* __restrict__ gs, const float* __restrict__ gb) {
    const float* x = (WHICH == 1) ? g_x1 : (WHICH == 2) ? g_x2 : g_x3;
    float* ab = (WHICH == 1) ? g_ab1 : (WHICH == 2) ? g_ab2 : g_ab3;
    float* dd = (WHICH == 1) ? g_dd1 : (WHICH == 2) ? g_dd2 : g_dd3;
    int b = blockIdx.x;
    int tid = threadIdx.x;              // 512 threads
    int c = tid % C;
    int tg = tid / C;
    const int TGS = 512 / C;
    const float* p = x + b * T_ * C + c;
    float s = 0.f, q = 0.f;
    for (int t = tg; t < T_; t += TGS) {
        float v = p[t * C];
        s += v; q = fmaf(v, v, q);
    }
    __shared__ float ss[512], sq[512];
    __shared__ float sS[C], sQ[C];
    ss[tid] = s; sq[tid] = q;
    __syncthreads();
    if (tid < C) {
        float S = 0.f, Q = 0.f;
        #pragma unroll
        for (int j = 0; j < TGS; j++) { S += ss[j * C + c]; Q += sq[j * C + c]; }
        sS[c] = S; sQ[c] = Q;
    }
    __syncthreads();
    if (tid < C) {
        int g0 = (c / G) * G;
        float S = 0.f, Q = 0.f;
        #pragma unroll
        for (int j = 0; j < G; j++) { S += sS[g0 + j]; Q += sQ[g0 + j]; }
        float n = (float)(G * T_);
        float mu = S / n;
        float var = Q / n - mu * mu;
        float a = rsqrtf(var + 1e-5f) * gs[c];
        ab[b * C + c] = a;
        dd[b * C + c] = gb[c] - mu * a;
    }
}

// ================ conv2: tf32 MMA, M=32 t, N=64 co, K=384 ================
// 4 warps: wm=wid&1 (m16), nh=wid>>1 (32 co = 4 ntiles). B chunks of 64 K-rows.
__global__ __launch_bounds__(128) void conv2_k(const float* __restrict__ bias) {
    __shared__ float sA[34 * 132];      // [t 0..33][ci 0..127], stride 132
    __shared__ float sB[64 * 72];       // [krow][co], stride 72
    int b = blockIdx.y, t0 = blockIdx.x * 32;
    int tid = threadIdx.x, lane = tid & 31, wid = tid >> 5;
    int wm = wid & 1, nh = wid >> 1;

    const float* ab = g_ab1 + b * 128;
    const float* dd = g_dd1 + b * 128;
    for (int i = tid; i < 34 * 128; i += 128) {
        int r = i >> 7, ci = i & 127;
        int t = t0 - 1 + r;
        float v = 0.f;
        if (t >= 0 && t < T_)
            v = fmaxf(fmaf(ab[ci], g_x1[(b * T_ + t) * 128 + ci], dd[ci]), 0.f);
        sA[r * 132 + ci] = tf32f(v);
    }

    float acc[4][4];
    #pragma unroll
    for (int nt = 0; nt < 4; nt++)
        #pragma unroll
        for (int j = 0; j < 4; j++) acc[nt][j] = 0.f;

    for (int c = 0; c < 6; c++) {           // tap=c>>1, ci base=(c&1)*64
        int tap = c >> 1, cib = (c & 1) * 64;
        __syncthreads();
        for (int i = tid; i < 64 * 64; i += 128) {
            int kr = i >> 6, co = i & 63;
            sB[kr * 72 + co] = g_w2t[((tap * 128 + cib) + kr) * 64 + co];
        }
        __syncthreads();
        int arow = 16 * wm + (lane >> 2) + tap;
        int bcol = nh * 32 + (lane >> 2);
        #pragma unroll
        for (int ks = 0; ks < 8; ks++) {
            int cb = cib + ks * 8 + (lane & 3);
            unsigned a0 = __float_as_uint(sA[arow * 132 + cb]);
            unsigned a1 = __float_as_uint(sA[(arow + 8) * 132 + cb]);
            unsigned a2 = __float_as_uint(sA[arow * 132 + cb + 4]);
            unsigned a3 = __float_as_uint(sA[(arow + 8) * 132 + cb + 4]);
            int brow = ks * 8 + (lane & 3);
            #pragma unroll
            for (int nt = 0; nt < 4; nt++) {
                unsigned b0 = __float_as_uint(sB[brow * 72 + bcol + nt * 8]);
                unsigned b1 = __float_as_uint(sB[(brow + 4) * 72 + bcol + nt * 8]);
                mma_tf32(acc[nt], a0, a1, a2, a3, b0, b1);
            }
        }
    }

    int trow = t0 + 16 * wm + (lane >> 2);
    int colb = nh * 32 + 2 * (lane & 3);
    #pragma unroll
    for (int nt = 0; nt < 4; nt++) {
        int col = colb + nt * 8;
        float2 bz = *(const float2*)(bias + col);
        int idx = (b * T_ + trow) * 64 + col;
        *(float2*)(g_x2 + idx) = make_float2(acc[nt][0] + bz.x, acc[nt][1] + bz.y);
        *(float2*)(g_x2 + idx + 8 * 64) = make_float2(acc[nt][2] + bz.x, acc[nt][3] + bz.y);
    }
}

// ================ conv3: tf32 MMA, M=64 t, N=32 co, K=192 (B fully resident) ================
// 4 warps: wm=wid (m16 each), full N=32 = 4 ntiles per warp.
__global__ __launch_bounds__(128) void conv3_k(const float* __restrict__ bias) {
    __shared__ float sA[66 * 68];       // [t 0..65][ci 0..63], stride 68
    __shared__ float sB[192 * 40];      // [krow 0..191][co], stride 40
    int b = blockIdx.y, t0 = blockIdx.x * 64;
    int tid = threadIdx.x, lane = tid & 31, wm = tid >> 5;

    const float* ab = g_ab2 + b * 64;
    const float* dd = g_dd2 + b * 64;
    for (int i = tid; i < 66 * 64; i += 128) {
        int r = i >> 6, ci = i & 63;
        int t = t0 - 1 + r;
        float v = 0.f;
        if (t >= 0 && t < T_)
            v = fmaxf(fmaf(ab[ci], g_x2[(b * T_ + t) * 64 + ci], dd[ci]), 0.f);
        sA[r * 68 + ci] = tf32f(v);
    }
    for (int i = tid; i < 192 * 32; i += 128) {
        int kr = i >> 5, co = i & 31;
        sB[kr * 40 + co] = g_w3t[kr * 32 + co];
    }
    __syncthreads();

    float acc[4][4];
    #pragma unroll
    for (int nt = 0; nt < 4; nt++)
        #pragma unroll
        for (int j = 0; j < 4; j++) acc[nt][j] = 0.f;

    #pragma unroll
    for (int tap = 0; tap < 3; tap++) {
        int arow = 16 * wm + (lane >> 2) + tap;
        int bcol = lane >> 2;
        #pragma unroll
        for (int ks = 0; ks < 8; ks++) {
            int cb = ks * 8 + (lane & 3);
            unsigned a0 = __float_as_uint(sA[arow * 68 + cb]);
            unsigned a1 = __float_as_uint(sA[(arow + 8) * 68 + cb]);
            unsigned a2 = __float_as_uint(sA[arow * 68 + cb + 4]);
            unsigned a3 = __float_as_uint(sA[(arow + 8) * 68 + cb + 4]);
            int brow = tap * 64 + ks * 8 + (lane & 3);
            #pragma unroll
            for (int nt = 0; nt < 4; nt++) {
                unsigned b0 = __float_as_uint(sB[brow * 40 + bcol + nt * 8]);
                unsigned b1 = __float_as_uint(sB[(brow + 4) * 40 + bcol + nt * 8]);
                mma_tf32(acc[nt], a0, a1, a2, a3, b0, b1);
            }
        }
    }

    int trow = t0 + 16 * wm + (lane >> 2);
    int colb = 2 * (lane & 3);
    #pragma unroll
    for (int nt = 0; nt < 4; nt++) {
        int col = colb + nt * 8;
        float2 bz = *(const float2*)(bias + col);
        int idx = (b * T_ + trow) * 32 + col;
        *(float2*)(g_x3 + idx) = make_float2(acc[nt][0] + bz.x, acc[nt][1] + bz.y);
        *(float2*)(g_x3 + idx + 8 * 32) = make_float2(acc[nt][2] + bz.x, acc[nt][3] + bz.y);
    }
}

// ---------------- final: GN3+relu + 1x1 conv + affine, warp per t ----------------
__global__ void final_k(const float* __restrict__ w4, const float* __restrict__ b4,
                        const float* __restrict__ mean, const float* __restrict__ stdv,
                        float* __restrict__ out) {
    int b = blockIdx.y;
    int w = threadIdx.x >> 5, lane = threadIdx.x & 31;
    float wv = w4[lane];
    float a = g_ab3[b * 32 + lane], d0 = g_dd3[b * 32 + lane];
    float bb = b4[0], me = mean[0], sc = stdv[0];
    int tbase = blockIdx.x * 128 + w * 16;
    for (int i = 0; i < 16; i++) {
        int t = tbase + i;
        float v = fmaxf(fmaf(a, g_x3[(b * T_ + t) * 32 + lane], d0), 0.f) * wv;
        #pragma unroll
        for (int off = 16; off; off >>= 1) v += __shfl_xor_sync(0xFFFFFFFFu, v, off);
        if (lane == 0) out[t * B_ + b] = fmaf(v + bb, sc, me);
    }
}

// ---------------- launcher ----------------
extern "C" void kernel_launch(void* const* d_in, const int* in_sizes, int n_in,
                              void* d_out, int out_size) {
    (void)in_sizes; (void)n_in; (void)out_size;
    const float* input      = (const float*)d_in[0];
    const float* g_style    = (const float*)d_in[1];
    const float* char_style = (const float*)d_in[3];
    const float* w1 = (const float*)d_in[4];
    const float* b1 = (const float*)d_in[5];
    const float* gs1 = (const float*)d_in[6];
    const float* gb1 = (const float*)d_in[7];
    const float* w2 = (const float*)d_in[8];
    const float* b2 = (const float*)d_in[9];
    const float* gs2 = (const float*)d_in[10];
    const float* gb2 = (const float*)d_in[11];
    const float* w3 = (const float*)d_in[12];
    const float* b3 = (const float*)d_in[13];
    const float* gs3 = (const float*)d_in[14];
    const float* gb3 = (const float*)d_in[15];
    const float* w4 = (const float*)d_in[16];
    const float* b4 = (const float*)d_in[17];
    const float* mean = (const float*)d_in[18];
    const float* stdv = (const float*)d_in[19];
    float* out = (float*)d_out;

    wtrans1_k<<<(128 * 400 * 3 + 255) / 256, 256>>>(w1);
    wtrans_k<<<(64 * 128 * 3 + 255) / 256, 256>>>(w2, 64, 128, 1);
    wtrans_k<<<(32 * 64 * 3 + 255) / 256, 256>>>(w3, 32, 64, 2);
    argmax_k<<<(T_ * B_ * 32) / 256, 256>>>(input);
    gpart_k<<<B_, 128>>>(g_style);
    stylepre_k<<<dim3(3, B_), 128>>>(char_style);
    add_k<<<dim3(T_, B_), 128>>>(b1);
    conv1_k<<<dim3(T_ / 64, B_), 256>>>(input);
    stats_k<128, 4, 1><<<B_, 512>>>(gs1, gb1);
    conv2_k<<<dim3(T_ / 32, B_), 128>>>(b2);
    stats_k<64, 2, 2><<<B_, 512>>>(gs2, gb2);
    conv3_k<<<dim3(T_ / 64, B_), 128>>>(b3);
    stats_k<32, 1, 3><<<B_, 512>>>(gs3, gb3);
    final_k<<<dim3(T_ / 128, B_), 256>>>(w4, b4, mean, stdv, out);
}